// round 7
// baseline (speedup 1.0000x reference)
#include <cuda_runtime.h>
#include <cuda_fp16.h>
#include <math.h>
#include <stdint.h>

// ---------------------------------------------------------------------------
// MoE top-2-of-8 via pure fp16 HMMA (fp32 accumulate).
// R7: 128x256 CTA tile, 2x4 warp grid, 64x64 warp tile (128 acc regs) to
// break the smem-bandwidth co-limit found in R6 (ldsm traffic 176KB/chunk
// vs 2M MACs -> smem 67% of HMMA time, tensor pipe becomes sole limiter).
//  - pass1: h = gelu(x @ w1[e]^T + b1[e]) -> h fp16
//  - pass2: out += p * (h @ w2[e]^T + b2[e])  (fp32 atomicAdd)
// ---------------------------------------------------------------------------

#define BATCH 8192
#define NEXP  8
#define DIN   2048
#define DHID  8192
#define DOUT  2048

#define BM 128
#define BN 256
#define MAX_ROWS 17408
#define NMT (MAX_ROWS / BM)

#define A_O 0
#define B_O 16384
#define STAGE_B 49152              // A 16KB + B 32KB
#define DYN_BYTES (3 * STAGE_B + 1024)

#define SWZ(o) ((o) ^ (((o) >> 3) & 0x70))

// ---- device scratch --------------------------------------------------------
__device__ __half g_w1h[(size_t)NEXP * DHID * DIN];
__device__ __half g_w2h[(size_t)NEXP * DOUT * DHID];
__device__ __half g_xh[(size_t)BATCH * DIN];
__device__ __half g_hh[(size_t)MAX_ROWS * DHID];

__device__ int   g_tok_e[BATCH * 2];
__device__ float g_tok_p[BATCH * 2];
__device__ int   g_pair_token[MAX_ROWS];
__device__ float g_pair_w[MAX_ROWS];
__device__ int   g_offsets[NEXP + 1];

// ---- helpers ----------------------------------------------------------------
__device__ __forceinline__ uint32_t smem_u32(const void* p) {
    uint32_t a;
    asm("{ .reg .u64 t; cvta.to.shared.u64 t, %1; cvt.u32.u64 %0, t; }"
        : "=r"(a) : "l"(p));
    return a;
}
__device__ __forceinline__ void cp16(uint32_t s, const void* g) {
    asm volatile("cp.async.cg.shared.global [%0], [%1], 16;" :: "r"(s), "l"(g));
}
__device__ __forceinline__ void cp_commit() {
    asm volatile("cp.async.commit_group;" ::: "memory");
}
template <int N>
__device__ __forceinline__ void cp_wait() {
    asm volatile("cp.async.wait_group %0;" :: "n"(N) : "memory");
}
__device__ __forceinline__ void ldsm4(uint32_t* r, uint32_t addr) {
    asm volatile("ldmatrix.sync.aligned.m8n8.x4.shared.b16 {%0,%1,%2,%3}, [%4];"
                 : "=r"(r[0]), "=r"(r[1]), "=r"(r[2]), "=r"(r[3]) : "r"(addr));
}
__device__ __forceinline__ void mma16816(float* d, const uint32_t* a,
                                         const uint32_t* b) {
    asm volatile(
        "mma.sync.aligned.m16n8k16.row.col.f32.f16.f16.f32 "
        "{%0,%1,%2,%3}, {%4,%5,%6,%7}, {%8,%9}, {%0,%1,%2,%3};"
        : "+f"(d[0]), "+f"(d[1]), "+f"(d[2]), "+f"(d[3])
        : "r"(a[0]), "r"(a[1]), "r"(a[2]), "r"(a[3]), "r"(b[0]), "r"(b[1]));
}
__device__ __forceinline__ float geluf(float v) {
    return 0.5f * v * (1.0f + erff(v * 0.7071067811865476f));
}

// ---------------------------------------------------------------------------
__global__ void init_kernel(float* __restrict__ out, int out_n) {
    int stride = gridDim.x * blockDim.x;
    int i0 = blockIdx.x * blockDim.x + threadIdx.x;
    for (int i = i0; i < out_n; i += stride) out[i] = 0.0f;
    for (int i = i0; i < MAX_ROWS; i += stride) {
        g_pair_token[i] = 0;
        g_pair_w[i] = 0.0f;
    }
}

__global__ void gate_kernel(const float* __restrict__ x,
                            const float* __restrict__ gw) {
    int gtid = blockIdx.x * blockDim.x + threadIdx.x;
    int t = gtid >> 5;
    int lane = gtid & 31;
    if (t >= BATCH) return;
    const float* xr = x + (size_t)t * DIN;
    float acc[NEXP];
#pragma unroll
    for (int e = 0; e < NEXP; e++) acc[e] = 0.0f;
    for (int k = lane; k < DIN; k += 32) {
        float xv = __ldg(xr + k);
#pragma unroll
        for (int e = 0; e < NEXP; e++) acc[e] += xv * __ldg(gw + e * DIN + k);
    }
#pragma unroll
    for (int off = 16; off > 0; off >>= 1) {
#pragma unroll
        for (int e = 0; e < NEXP; e++)
            acc[e] += __shfl_xor_sync(0xffffffffu, acc[e], off);
    }
    if (lane == 0) {
        float v0 = -1e30f, v1 = -1e30f;
        int i0 = 0, i1 = 0;
#pragma unroll
        for (int e = 0; e < NEXP; e++) {
            float v = acc[e];
            if (v > v0) { v1 = v0; i1 = i0; v0 = v; i0 = e; }
            else if (v > v1) { v1 = v; i1 = e; }
        }
        float e1 = expf(v1 - v0);
        float s = 1.0f + e1;
        g_tok_e[2 * t + 0] = i0;
        g_tok_e[2 * t + 1] = i1;
        g_tok_p[2 * t + 0] = 1.0f / s;
        g_tok_p[2 * t + 1] = e1 / s;
    }
}

__global__ void offsets_kernel() {
    __shared__ int cnt[NEXP];
    if (threadIdx.x < NEXP) cnt[threadIdx.x] = 0;
    __syncthreads();
    for (int t = threadIdx.x; t < BATCH; t += blockDim.x) {
        atomicAdd(&cnt[g_tok_e[2 * t + 0]], 1);
        atomicAdd(&cnt[g_tok_e[2 * t + 1]], 1);
    }
    __syncthreads();
    if (threadIdx.x == 0) {
        int off = 0;
        for (int e = 0; e < NEXP; e++) {
            g_offsets[e] = off;
            off += ((cnt[e] + BM - 1) / BM) * BM;
        }
        g_offsets[NEXP] = off;
    }
}

__global__ void assign_kernel() {
    int e = blockIdx.x;
    __shared__ int wcnt[8];
    __shared__ int sbase;
    if (threadIdx.x == 0) sbase = g_offsets[e];
    __syncthreads();
    int base = sbase;
    int lane = threadIdx.x & 31;
    int wid = threadIdx.x >> 5;
    for (int t0 = 0; t0 < BATCH; t0 += 256) {
        int t = t0 + threadIdx.x;
        int sel = 0;
        float w = 0.0f;
        int e0 = g_tok_e[2 * t], e1 = g_tok_e[2 * t + 1];
        if (e0 == e)      { sel = 1; w = g_tok_p[2 * t]; }
        else if (e1 == e) { sel = 1; w = g_tok_p[2 * t + 1]; }
        unsigned m = __ballot_sync(0xffffffffu, sel);
        if (lane == 0) wcnt[wid] = __popc(m);
        __syncthreads();
        int prefix = 0, tot = 0;
#pragma unroll
        for (int i = 0; i < 8; i++) {
            if (i < wid) prefix += wcnt[i];
            tot += wcnt[i];
        }
        if (sel) {
            int pos = base + prefix + __popc(m & ((1u << lane) - 1u));
            g_pair_token[pos] = t;
            g_pair_w[pos] = w;
        }
        base += tot;
        __syncthreads();
    }
}

// fp32 -> fp16 (which: 0=w1, 1=w2, 2=x)
__global__ void conv_h16(const float4* __restrict__ src, size_t n4, int which) {
    uint2* dst;
    if (which == 0)      dst = (uint2*)g_w1h;
    else if (which == 1) dst = (uint2*)g_w2h;
    else                 dst = (uint2*)g_xh;
    size_t i = (size_t)blockIdx.x * blockDim.x + threadIdx.x;
    size_t stride = (size_t)gridDim.x * blockDim.x;
    for (; i < n4; i += stride) {
        float4 v = src[i];
        __half2 h0 = __floats2half2_rn(v.x, v.y);
        __half2 h1 = __floats2half2_rn(v.z, v.w);
        dst[i] = make_uint2(*(uint32_t*)&h0, *(uint32_t*)&h1);
    }
}

// ---------------------------------------------------------------------------
// Grouped GEMM: C[128x256] = A[128xK] * B[256xK]^T, fp16 HMMA.
// 8 warps, 2x4 warp grid, 64x64 warp tile.
// P1: A = x fp16 (token gather), B = w1 fp16, epilogue gelu -> h fp16.
// P2: A = h fp16 (direct rows),  B = w2 fp16, epilogue atomicAdd out.
// ---------------------------------------------------------------------------
template <int KDIM, bool P1>
__global__ void __launch_bounds__(256, 1)
mma_gemm(const float* __restrict__ bias, float* __restrict__ out) {
    const int mt = P1 ? blockIdx.x : blockIdx.y;
    const int nt = P1 ? blockIdx.y : blockIdx.x;
    __shared__ int s_off[NEXP + 1];
    __shared__ int stok[BM];
    __shared__ float ssw[BM];
    __shared__ float sbias[BN];
    extern __shared__ char dsm[];

    const int tid = threadIdx.x;
    if (tid < NEXP + 1) s_off[tid] = g_offsets[tid];
    __syncthreads();
    const int row0 = mt * BM;
    if (row0 >= s_off[NEXP]) return;
    int e = 0;
    while (row0 >= s_off[e + 1]) e++;
    if (tid < BM) {
        stok[tid] = g_pair_token[row0 + tid];
        ssw[tid] = g_pair_w[row0 + tid];
    }
    sbias[tid] = bias[(size_t)e * (P1 ? DHID : DOUT) + (size_t)nt * BN + tid];
    __syncthreads();

    const __half* Ag = P1 ? g_xh : g_hh;
    const __half* Bg = P1 ? g_w1h : g_w2h;

    uintptr_t pal = ((uintptr_t)dsm + 1023) & ~(uintptr_t)1023;
    const uint32_t su = smem_u32((void*)pal);

    // ---- producer mapping: ch = k-16B-chunk (0..7), rb = row group (0..31)
    const int ch = tid & 7;
    const int rb = tid >> 3;
    const __half* aP[4];                 // A rows rb + i*32 (gather for P1)
    const size_t brow0 = (size_t)e * (P1 ? DHID : DOUT) + (size_t)nt * BN;
    const __half* bP0 = Bg + (brow0 + rb) * (size_t)KDIM + ch * 8;  // +i*32*KDIM
#pragma unroll
    for (int i = 0; i < 4; i++) {
        int r = rb + i * 32;
        size_t ga = P1 ? (size_t)stok[r] * KDIM : (size_t)(row0 + r) * KDIM;
        aP[i] = Ag + ga + ch * 8;
    }
    const uint32_t swz0 = SWZ((uint32_t)rb * 128 + (uint32_t)ch * 16);

    auto issue = [&](int kt, int st) {
        uint32_t sb = su + st * STAGE_B;
        int ko = kt * 64;
#pragma unroll
        for (int i = 0; i < 4; i++)
            cp16(sb + A_O + swz0 + i * 4096, aP[i] + ko);
#pragma unroll
        for (int i = 0; i < 8; i++)
            cp16(sb + B_O + swz0 + i * 4096, bP0 + (size_t)i * 32 * KDIM + ko);
    };

    issue(0, 0);
    cp_commit();
    issue(1, 1);
    cp_commit();

    // ---- consumer mapping: 2x4 warp grid, warp tile 64x64 ----
    const int wid = tid >> 5, lane = tid & 31;
    const int warp_m = (wid >> 2) * 64;
    const int warp_n = (wid & 3) * 64;
    const uint32_t xorv = (uint32_t)(lane & 7) << 4;
    const uint32_t kx = (uint32_t)((lane >> 4) << 4);
    const uint32_t rowA =
        (uint32_t)(warp_m + (lane & 7) + ((lane >> 3) & 1) * 8) * 128;
    const uint32_t rowB =
        (uint32_t)(warp_n + (lane & 7) + ((lane >> 3) & 1) * 8) * 128;

    float acc[4][8][4];
#pragma unroll
    for (int i = 0; i < 4; i++)
#pragma unroll
        for (int j = 0; j < 8; j++)
#pragma unroll
            for (int q = 0; q < 4; q++) acc[i][j][q] = 0.0f;

    const int NCH = KDIM / 64;
#pragma unroll 1
    for (int c = 0; c < NCH; c++) {
        cp_wait<1>();
        __syncthreads();
        if (c + 2 < NCH) issue(c + 2, (c + 2) % 3);
        cp_commit();
        const uint32_t sb = su + (c % 3) * STAGE_B;
#pragma unroll
        for (int s = 0; s < 4; s++) {
            const uint32_t kt = (((uint32_t)(s * 32)) + kx) ^ xorv;
            uint32_t ah[4][4], bh[4][4];
#pragma unroll
            for (int mi = 0; mi < 4; mi++)
                ldsm4(ah[mi], sb + A_O + rowA + mi * 2048 + kt);
#pragma unroll
            for (int j = 0; j < 4; j++)
                ldsm4(bh[j], sb + B_O + rowB + j * 2048 + kt);
#pragma unroll
            for (int mi = 0; mi < 4; mi++)
#pragma unroll
                for (int nj = 0; nj < 8; nj++) {
                    uint32_t bhi[2] = {bh[nj >> 1][nj & 1], bh[nj >> 1][(nj & 1) + 2]};
                    mma16816(acc[mi][nj], ah[mi], bhi);
                }
        }
    }

    // ---- epilogue ----
    const int g = lane >> 2, t4 = lane & 3;
    if (P1) {
#pragma unroll
        for (int mi = 0; mi < 4; mi++) {
            int r0 = warp_m + mi * 16 + g;
#pragma unroll
            for (int nj = 0; nj < 8; nj++) {
                int cB = warp_n + nj * 8 + 2 * t4;
                float b0v = sbias[cB], b1v = sbias[cB + 1];
                float v00 = geluf(acc[mi][nj][0] + b0v);
                float v01 = geluf(acc[mi][nj][1] + b1v);
                float v10 = geluf(acc[mi][nj][2] + b0v);
                float v11 = geluf(acc[mi][nj][3] + b1v);
                size_t gc = (size_t)nt * BN + cB;
                __half2 p0 = __floats2half2_rn(v00, v01);
                __half2 p1 = __floats2half2_rn(v10, v11);
                *(uint32_t*)(g_hh + (size_t)(row0 + r0) * DHID + gc) =
                    *(uint32_t*)&p0;
                *(uint32_t*)(g_hh + (size_t)(row0 + r0 + 8) * DHID + gc) =
                    *(uint32_t*)&p1;
            }
        }
    } else {
#pragma unroll
        for (int mi = 0; mi < 4; mi++) {
            int r0 = warp_m + mi * 16 + g;
            int tok0 = stok[r0], tok1 = stok[r0 + 8];
            float w0 = ssw[r0], w1 = ssw[r0 + 8];
            float* o0 = out + (size_t)tok0 * DOUT + (size_t)nt * BN;
            float* o1 = out + (size_t)tok1 * DOUT + (size_t)nt * BN;
#pragma unroll
            for (int nj = 0; nj < 8; nj++) {
                int cB = warp_n + nj * 8 + 2 * t4;
                float b0v = sbias[cB], b1v = sbias[cB + 1];
                atomicAdd(o0 + cB,     w0 * (acc[mi][nj][0] + b0v));
                atomicAdd(o0 + cB + 1, w0 * (acc[mi][nj][1] + b1v));
                atomicAdd(o1 + cB,     w1 * (acc[mi][nj][2] + b0v));
                atomicAdd(o1 + cB + 1, w1 * (acc[mi][nj][3] + b1v));
            }
        }
    }
}

// ---------------------------------------------------------------------------
extern "C" void kernel_launch(void* const* d_in, const int* in_sizes, int n_in,
                              void* d_out, int out_size) {
    const float* x  = (const float*)d_in[0];
    const float* gw = (const float*)d_in[1];
    const float* w1 = (const float*)d_in[2];
    const float* b1 = (const float*)d_in[3];
    const float* w2 = (const float*)d_in[4];
    const float* b2 = (const float*)d_in[5];
    float* out = (float*)d_out;

    cudaFuncSetAttribute(mma_gemm<DIN, true>,
                         cudaFuncAttributeMaxDynamicSharedMemorySize, DYN_BYTES);
    cudaFuncSetAttribute(mma_gemm<DHID, false>,
                         cudaFuncAttributeMaxDynamicSharedMemorySize, DYN_BYTES);

    init_kernel<<<2048, 256>>>(out, out_size);
    gate_kernel<<<(BATCH * 32 + 255) / 256, 256>>>(x, gw);
    offsets_kernel<<<1, 256>>>();
    assign_kernel<<<NEXP, 256>>>();

    size_t n4x = (size_t)BATCH * DIN / 4;
    size_t n4w1 = (size_t)NEXP * DHID * DIN / 4;
    size_t n4w2 = (size_t)NEXP * DOUT * DHID / 4;
    conv_h16<<<(int)((n4x + 255) / 256), 256>>>((const float4*)x, n4x, 2);
    conv_h16<<<32768, 256>>>((const float4*)w1, n4w1, 0);
    conv_h16<<<32768, 256>>>((const float4*)w2, n4w2, 1);

    mma_gemm<DIN, true><<<dim3(NMT, DHID / BN), 256, DYN_BYTES>>>(b1, nullptr);
    mma_gemm<DHID, false><<<dim3(DOUT / BN, NMT), 256, DYN_BYTES>>>(b2, out);
}

// round 8
// speedup vs baseline: 1.0702x; 1.0702x over previous
#include <cuda_runtime.h>
#include <cuda_fp16.h>
#include <math.h>
#include <stdint.h>

// ---------------------------------------------------------------------------
// MoE top-2-of-8 via pure fp16 HMMA (fp32 accumulate).
// R8: 128x128 CTA tile, 2x2 warp grid of 64x64 warp tiles, 128 threads,
// 2 CTAs/SM. Combines R6's occupancy (2 CTAs hiding barriers) with R7's
// square warp tiles (96KB smem/chunk vs 128KB -> smem no longer co-limits).
//  - pass1: h = gelu(x @ w1[e]^T + b1[e]) -> h fp16
//  - pass2: out += p * (h @ w2[e]^T + b2[e])  (fp32 atomicAdd)
// ---------------------------------------------------------------------------

#define BATCH 8192
#define NEXP  8
#define DIN   2048
#define DHID  8192
#define DOUT  2048

#define BM 128
#define BN 128
#define MAX_ROWS 17408
#define NMT (MAX_ROWS / BM)

#define A_O 0
#define B_O 16384
#define STAGE_B 32768
#define DYN_BYTES (3 * STAGE_B + 1024)

#define SWZ(o) ((o) ^ (((o) >> 3) & 0x70))

// ---- device scratch --------------------------------------------------------
__device__ __half g_w1h[(size_t)NEXP * DHID * DIN];
__device__ __half g_w2h[(size_t)NEXP * DOUT * DHID];
__device__ __half g_xh[(size_t)BATCH * DIN];
__device__ __half g_hh[(size_t)MAX_ROWS * DHID];

__device__ int   g_tok_e[BATCH * 2];
__device__ float g_tok_p[BATCH * 2];
__device__ int   g_pair_token[MAX_ROWS];
__device__ float g_pair_w[MAX_ROWS];
__device__ int   g_offsets[NEXP + 1];

// ---- helpers ----------------------------------------------------------------
__device__ __forceinline__ uint32_t smem_u32(const void* p) {
    uint32_t a;
    asm("{ .reg .u64 t; cvta.to.shared.u64 t, %1; cvt.u32.u64 %0, t; }"
        : "=r"(a) : "l"(p));
    return a;
}
__device__ __forceinline__ void cp16(uint32_t s, const void* g) {
    asm volatile("cp.async.cg.shared.global [%0], [%1], 16;" :: "r"(s), "l"(g));
}
__device__ __forceinline__ void cp_commit() {
    asm volatile("cp.async.commit_group;" ::: "memory");
}
template <int N>
__device__ __forceinline__ void cp_wait() {
    asm volatile("cp.async.wait_group %0;" :: "n"(N) : "memory");
}
__device__ __forceinline__ void ldsm4(uint32_t* r, uint32_t addr) {
    asm volatile("ldmatrix.sync.aligned.m8n8.x4.shared.b16 {%0,%1,%2,%3}, [%4];"
                 : "=r"(r[0]), "=r"(r[1]), "=r"(r[2]), "=r"(r[3]) : "r"(addr));
}
__device__ __forceinline__ void mma16816(float* d, const uint32_t* a,
                                         const uint32_t* b) {
    asm volatile(
        "mma.sync.aligned.m16n8k16.row.col.f32.f16.f16.f32 "
        "{%0,%1,%2,%3}, {%4,%5,%6,%7}, {%8,%9}, {%0,%1,%2,%3};"
        : "+f"(d[0]), "+f"(d[1]), "+f"(d[2]), "+f"(d[3])
        : "r"(a[0]), "r"(a[1]), "r"(a[2]), "r"(a[3]), "r"(b[0]), "r"(b[1]));
}
__device__ __forceinline__ float geluf(float v) {
    return 0.5f * v * (1.0f + erff(v * 0.7071067811865476f));
}

// ---------------------------------------------------------------------------
__global__ void init_kernel(float* __restrict__ out, int out_n) {
    int stride = gridDim.x * blockDim.x;
    int i0 = blockIdx.x * blockDim.x + threadIdx.x;
    for (int i = i0; i < out_n; i += stride) out[i] = 0.0f;
    for (int i = i0; i < MAX_ROWS; i += stride) {
        g_pair_token[i] = 0;
        g_pair_w[i] = 0.0f;
    }
}

__global__ void gate_kernel(const float* __restrict__ x,
                            const float* __restrict__ gw) {
    int gtid = blockIdx.x * blockDim.x + threadIdx.x;
    int t = gtid >> 5;
    int lane = gtid & 31;
    if (t >= BATCH) return;
    const float* xr = x + (size_t)t * DIN;
    float acc[NEXP];
#pragma unroll
    for (int e = 0; e < NEXP; e++) acc[e] = 0.0f;
    for (int k = lane; k < DIN; k += 32) {
        float xv = __ldg(xr + k);
#pragma unroll
        for (int e = 0; e < NEXP; e++) acc[e] += xv * __ldg(gw + e * DIN + k);
    }
#pragma unroll
    for (int off = 16; off > 0; off >>= 1) {
#pragma unroll
        for (int e = 0; e < NEXP; e++)
            acc[e] += __shfl_xor_sync(0xffffffffu, acc[e], off);
    }
    if (lane == 0) {
        float v0 = -1e30f, v1 = -1e30f;
        int i0 = 0, i1 = 0;
#pragma unroll
        for (int e = 0; e < NEXP; e++) {
            float v = acc[e];
            if (v > v0) { v1 = v0; i1 = i0; v0 = v; i0 = e; }
            else if (v > v1) { v1 = v; i1 = e; }
        }
        float e1 = expf(v1 - v0);
        float s = 1.0f + e1;
        g_tok_e[2 * t + 0] = i0;
        g_tok_e[2 * t + 1] = i1;
        g_tok_p[2 * t + 0] = 1.0f / s;
        g_tok_p[2 * t + 1] = e1 / s;
    }
}

__global__ void offsets_kernel() {
    __shared__ int cnt[NEXP];
    if (threadIdx.x < NEXP) cnt[threadIdx.x] = 0;
    __syncthreads();
    for (int t = threadIdx.x; t < BATCH; t += blockDim.x) {
        atomicAdd(&cnt[g_tok_e[2 * t + 0]], 1);
        atomicAdd(&cnt[g_tok_e[2 * t + 1]], 1);
    }
    __syncthreads();
    if (threadIdx.x == 0) {
        int off = 0;
        for (int e = 0; e < NEXP; e++) {
            g_offsets[e] = off;
            off += ((cnt[e] + BM - 1) / BM) * BM;
        }
        g_offsets[NEXP] = off;
    }
}

__global__ void assign_kernel() {
    int e = blockIdx.x;
    __shared__ int wcnt[8];
    __shared__ int sbase;
    if (threadIdx.x == 0) sbase = g_offsets[e];
    __syncthreads();
    int base = sbase;
    int lane = threadIdx.x & 31;
    int wid = threadIdx.x >> 5;
    for (int t0 = 0; t0 < BATCH; t0 += 256) {
        int t = t0 + threadIdx.x;
        int sel = 0;
        float w = 0.0f;
        int e0 = g_tok_e[2 * t], e1 = g_tok_e[2 * t + 1];
        if (e0 == e)      { sel = 1; w = g_tok_p[2 * t]; }
        else if (e1 == e) { sel = 1; w = g_tok_p[2 * t + 1]; }
        unsigned m = __ballot_sync(0xffffffffu, sel);
        if (lane == 0) wcnt[wid] = __popc(m);
        __syncthreads();
        int prefix = 0, tot = 0;
#pragma unroll
        for (int i = 0; i < 8; i++) {
            if (i < wid) prefix += wcnt[i];
            tot += wcnt[i];
        }
        if (sel) {
            int pos = base + prefix + __popc(m & ((1u << lane) - 1u));
            g_pair_token[pos] = t;
            g_pair_w[pos] = w;
        }
        base += tot;
        __syncthreads();
    }
}

// fp32 -> fp16 (which: 0=w1, 1=w2, 2=x)
__global__ void conv_h16(const float4* __restrict__ src, size_t n4, int which) {
    uint2* dst;
    if (which == 0)      dst = (uint2*)g_w1h;
    else if (which == 1) dst = (uint2*)g_w2h;
    else                 dst = (uint2*)g_xh;
    size_t i = (size_t)blockIdx.x * blockDim.x + threadIdx.x;
    size_t stride = (size_t)gridDim.x * blockDim.x;
    for (; i < n4; i += stride) {
        float4 v = src[i];
        __half2 h0 = __floats2half2_rn(v.x, v.y);
        __half2 h1 = __floats2half2_rn(v.z, v.w);
        dst[i] = make_uint2(*(uint32_t*)&h0, *(uint32_t*)&h1);
    }
}

// ---------------------------------------------------------------------------
// Grouped GEMM: C[128x128] = A[128xK] * B[128xK]^T, fp16 HMMA.
// 4 warps (128 threads), 2x2 warp grid, 64x64 warp tile, 2 CTAs/SM.
// P1: A = x fp16 (token gather), B = w1 fp16, epilogue gelu -> h fp16.
// P2: A = h fp16 (direct rows),  B = w2 fp16, epilogue atomicAdd out.
// ---------------------------------------------------------------------------
template <int KDIM, bool P1>
__global__ void __launch_bounds__(128, 2)
mma_gemm(const float* __restrict__ bias, float* __restrict__ out) {
    const int mt = P1 ? blockIdx.x : blockIdx.y;
    const int nt = P1 ? blockIdx.y : blockIdx.x;
    __shared__ int s_off[NEXP + 1];
    __shared__ int stok[BM];
    __shared__ float ssw[BM];
    __shared__ float sbias[BN];
    extern __shared__ char dsm[];

    const int tid = threadIdx.x;
    if (tid < NEXP + 1) s_off[tid] = g_offsets[tid];
    __syncthreads();
    const int row0 = mt * BM;
    if (row0 >= s_off[NEXP]) return;
    int e = 0;
    while (row0 >= s_off[e + 1]) e++;
    stok[tid] = g_pair_token[row0 + tid];
    ssw[tid] = g_pair_w[row0 + tid];
    sbias[tid] = bias[(size_t)e * (P1 ? DHID : DOUT) + (size_t)nt * BN + tid];
    __syncthreads();

    const __half* Ag = P1 ? g_xh : g_hh;
    const __half* Bg = P1 ? g_w1h : g_w2h;

    uintptr_t pal = ((uintptr_t)dsm + 1023) & ~(uintptr_t)1023;
    const uint32_t su = smem_u32((void*)pal);

    // ---- producer mapping: ch = k-16B-chunk (0..7), rb = row group (0..15)
    // each thread loads 8 A rows + 8 B rows (rb + i*16), one 16B chunk each.
    const int ch = tid & 7;
    const int rb = tid >> 3;
    const __half* aP[8];
    const size_t brow0 = (size_t)e * (P1 ? DHID : DOUT) + (size_t)nt * BN;
    const __half* bP0 = Bg + (brow0 + rb) * (size_t)KDIM + ch * 8;
#pragma unroll
    for (int i = 0; i < 8; i++) {
        int r = rb + i * 16;
        size_t ga = P1 ? (size_t)stok[r] * KDIM : (size_t)(row0 + r) * KDIM;
        aP[i] = Ag + ga + ch * 8;
    }
    const uint32_t swz0 = SWZ((uint32_t)rb * 128 + (uint32_t)ch * 16);

    auto issue = [&](int kt, int st) {
        uint32_t sb = su + st * STAGE_B;
        int ko = kt * 64;
#pragma unroll
        for (int i = 0; i < 8; i++)
            cp16(sb + A_O + swz0 + i * 2048, aP[i] + ko);
#pragma unroll
        for (int i = 0; i < 8; i++)
            cp16(sb + B_O + swz0 + i * 2048, bP0 + (size_t)i * 16 * KDIM + ko);
    };

    issue(0, 0);
    cp_commit();
    issue(1, 1);
    cp_commit();

    // ---- consumer mapping: 2x2 warp grid, warp tile 64x64 ----
    const int wid = tid >> 5, lane = tid & 31;
    const int warp_m = (wid >> 1) * 64;
    const int warp_n = (wid & 1) * 64;
    const uint32_t xorv = (uint32_t)(lane & 7) << 4;
    const uint32_t kx = (uint32_t)((lane >> 4) << 4);
    const uint32_t rowA =
        (uint32_t)(warp_m + (lane & 7) + ((lane >> 3) & 1) * 8) * 128;
    const uint32_t rowB =
        (uint32_t)(warp_n + (lane & 7) + ((lane >> 3) & 1) * 8) * 128;

    float acc[4][8][4];
#pragma unroll
    for (int i = 0; i < 4; i++)
#pragma unroll
        for (int j = 0; j < 8; j++)
#pragma unroll
            for (int q = 0; q < 4; q++) acc[i][j][q] = 0.0f;

    const int NCH = KDIM / 64;
#pragma unroll 1
    for (int c = 0; c < NCH; c++) {
        cp_wait<1>();
        __syncthreads();
        if (c + 2 < NCH) issue(c + 2, (c + 2) % 3);
        cp_commit();
        const uint32_t sb = su + (c % 3) * STAGE_B;
#pragma unroll
        for (int s = 0; s < 4; s++) {
            const uint32_t kt = (((uint32_t)(s * 32)) + kx) ^ xorv;
            uint32_t ah[4][4], bh[4][4];
#pragma unroll
            for (int mi = 0; mi < 4; mi++)
                ldsm4(ah[mi], sb + A_O + rowA + mi * 2048 + kt);
#pragma unroll
            for (int j = 0; j < 4; j++)
                ldsm4(bh[j], sb + B_O + rowB + j * 2048 + kt);
#pragma unroll
            for (int mi = 0; mi < 4; mi++)
#pragma unroll
                for (int nj = 0; nj < 8; nj++) {
                    uint32_t bhi[2] = {bh[nj >> 1][nj & 1], bh[nj >> 1][(nj & 1) + 2]};
                    mma16816(acc[mi][nj], ah[mi], bhi);
                }
        }
    }

    // ---- epilogue ----
    const int g = lane >> 2, t4 = lane & 3;
    if (P1) {
#pragma unroll
        for (int mi = 0; mi < 4; mi++) {
            int r0 = warp_m + mi * 16 + g;
#pragma unroll
            for (int nj = 0; nj < 8; nj++) {
                int cB = warp_n + nj * 8 + 2 * t4;
                float b0v = sbias[cB], b1v = sbias[cB + 1];
                float v00 = geluf(acc[mi][nj][0] + b0v);
                float v01 = geluf(acc[mi][nj][1] + b1v);
                float v10 = geluf(acc[mi][nj][2] + b0v);
                float v11 = geluf(acc[mi][nj][3] + b1v);
                size_t gc = (size_t)nt * BN + cB;
                __half2 p0 = __floats2half2_rn(v00, v01);
                __half2 p1 = __floats2half2_rn(v10, v11);
                *(uint32_t*)(g_hh + (size_t)(row0 + r0) * DHID + gc) =
                    *(uint32_t*)&p0;
                *(uint32_t*)(g_hh + (size_t)(row0 + r0 + 8) * DHID + gc) =
                    *(uint32_t*)&p1;
            }
        }
    } else {
#pragma unroll
        for (int mi = 0; mi < 4; mi++) {
            int r0 = warp_m + mi * 16 + g;
            int tok0 = stok[r0], tok1 = stok[r0 + 8];
            float w0 = ssw[r0], w1 = ssw[r0 + 8];
            float* o0 = out + (size_t)tok0 * DOUT + (size_t)nt * BN;
            float* o1 = out + (size_t)tok1 * DOUT + (size_t)nt * BN;
#pragma unroll
            for (int nj = 0; nj < 8; nj++) {
                int cB = warp_n + nj * 8 + 2 * t4;
                float b0v = sbias[cB], b1v = sbias[cB + 1];
                atomicAdd(o0 + cB,     w0 * (acc[mi][nj][0] + b0v));
                atomicAdd(o0 + cB + 1, w0 * (acc[mi][nj][1] + b1v));
                atomicAdd(o1 + cB,     w1 * (acc[mi][nj][2] + b0v));
                atomicAdd(o1 + cB + 1, w1 * (acc[mi][nj][3] + b1v));
            }
        }
    }
}

// ---------------------------------------------------------------------------
extern "C" void kernel_launch(void* const* d_in, const int* in_sizes, int n_in,
                              void* d_out, int out_size) {
    const float* x  = (const float*)d_in[0];
    const float* gw = (const float*)d_in[1];
    const float* w1 = (const float*)d_in[2];
    const float* b1 = (const float*)d_in[3];
    const float* w2 = (const float*)d_in[4];
    const float* b2 = (const float*)d_in[5];
    float* out = (float*)d_out;

    cudaFuncSetAttribute(mma_gemm<DIN, true>,
                         cudaFuncAttributeMaxDynamicSharedMemorySize, DYN_BYTES);
    cudaFuncSetAttribute(mma_gemm<DHID, false>,
                         cudaFuncAttributeMaxDynamicSharedMemorySize, DYN_BYTES);

    init_kernel<<<2048, 256>>>(out, out_size);
    gate_kernel<<<(BATCH * 32 + 255) / 256, 256>>>(x, gw);
    offsets_kernel<<<1, 256>>>();
    assign_kernel<<<NEXP, 256>>>();

    size_t n4x = (size_t)BATCH * DIN / 4;
    size_t n4w1 = (size_t)NEXP * DHID * DIN / 4;
    size_t n4w2 = (size_t)NEXP * DOUT * DHID / 4;
    conv_h16<<<(int)((n4x + 255) / 256), 256>>>((const float4*)x, n4x, 2);
    conv_h16<<<32768, 256>>>((const float4*)w1, n4w1, 0);
    conv_h16<<<32768, 256>>>((const float4*)w2, n4w2, 1);

    mma_gemm<DIN, true><<<dim3(NMT, DHID / BN), 128, DYN_BYTES>>>(b1, nullptr);
    mma_gemm<DHID, false><<<dim3(DOUT / BN, NMT), 128, DYN_BYTES>>>(b2, out);
}

// round 9
// speedup vs baseline: 1.0815x; 1.0106x over previous
#include <cuda_runtime.h>
#include <cuda_fp16.h>
#include <math.h>
#include <stdint.h>

// ---------------------------------------------------------------------------
// MoE top-2-of-8 via pure fp16 HMMA (fp32 accumulate).
// R9: overhead attack. GEMM geometry unchanged from R8 (128x128 CTA, 2x2
// warps of 64x64, 2 CTAs/SM):
//  - w1/x fp32->fp16 conversion fused into gate kernel's grid (overlap)
//  - w2 conversion fused into pass1's grid (pass1 never reads w2)
//  - pass2 writes y-scratch with plain stores; combine kernel does
//    out[t] = p0*y[slot0] + p1*y[slot1]  (no atomics, no out zero-init)
// ---------------------------------------------------------------------------

#define BATCH 8192
#define NEXP  8
#define DIN   2048
#define DHID  8192
#define DOUT  2048

#define BM 128
#define BN 128
#define MAX_ROWS 17408
#define NMT (MAX_ROWS / BM)

#define A_O 0
#define B_O 16384
#define STAGE_B 32768
#define DYN_BYTES (3 * STAGE_B + 1024)

#define GATE_B 1024            // gating blocks (8192 tokens, 8 warps/block)
#define W1CONV_B 2048          // w1 converter blocks in gate grid
#define XCONV_B 256            // x converter blocks in gate grid
#define W2CONV_X 64            // extra grid.x rows in pass1 (x64 y = 4096 blocks)

#define SWZ(o) ((o) ^ (((o) >> 3) & 0x70))

// ---- device scratch --------------------------------------------------------
__device__ __half g_w1h[(size_t)NEXP * DHID * DIN];
__device__ __half g_w2h[(size_t)NEXP * DOUT * DHID];
__device__ __half g_xh[(size_t)BATCH * DIN];
__device__ __half g_hh[(size_t)MAX_ROWS * DHID];
__device__ float  g_y[(size_t)MAX_ROWS * DOUT];    // pass2 per-slot output

__device__ int   g_tok_e[BATCH * 2];
__device__ float g_tok_p[BATCH * 2];
__device__ int   g_tok_slot[BATCH * 2];
__device__ int   g_pair_token[MAX_ROWS];
__device__ int   g_offsets[NEXP + 1];

// ---- helpers ----------------------------------------------------------------
__device__ __forceinline__ uint32_t smem_u32(const void* p) {
    uint32_t a;
    asm("{ .reg .u64 t; cvta.to.shared.u64 t, %1; cvt.u32.u64 %0, t; }"
        : "=r"(a) : "l"(p));
    return a;
}
__device__ __forceinline__ void cp16(uint32_t s, const void* g) {
    asm volatile("cp.async.cg.shared.global [%0], [%1], 16;" :: "r"(s), "l"(g));
}
__device__ __forceinline__ void cp_commit() {
    asm volatile("cp.async.commit_group;" ::: "memory");
}
template <int N>
__device__ __forceinline__ void cp_wait() {
    asm volatile("cp.async.wait_group %0;" :: "n"(N) : "memory");
}
__device__ __forceinline__ void ldsm4(uint32_t* r, uint32_t addr) {
    asm volatile("ldmatrix.sync.aligned.m8n8.x4.shared.b16 {%0,%1,%2,%3}, [%4];"
                 : "=r"(r[0]), "=r"(r[1]), "=r"(r[2]), "=r"(r[3]) : "r"(addr));
}
__device__ __forceinline__ void mma16816(float* d, const uint32_t* a,
                                         const uint32_t* b) {
    asm volatile(
        "mma.sync.aligned.m16n8k16.row.col.f32.f16.f16.f32 "
        "{%0,%1,%2,%3}, {%4,%5,%6,%7}, {%8,%9}, {%0,%1,%2,%3};"
        : "+f"(d[0]), "+f"(d[1]), "+f"(d[2]), "+f"(d[3])
        : "r"(a[0]), "r"(a[1]), "r"(a[2]), "r"(a[3]), "r"(b[0]), "r"(b[1]));
}
__device__ __forceinline__ float geluf(float v) {
    return 0.5f * v * (1.0f + erff(v * 0.7071067811865476f));
}
__device__ __forceinline__ void conv4(const float4* __restrict__ src,
                                      uint2* __restrict__ dst, size_t i) {
    float4 v = src[i];
    __half2 h0 = __floats2half2_rn(v.x, v.y);
    __half2 h1 = __floats2half2_rn(v.z, v.w);
    dst[i] = make_uint2(*(uint32_t*)&h0, *(uint32_t*)&h1);
}

// ---------------------------------------------------------------------------
__global__ void init_kernel() {
    int i = blockIdx.x * blockDim.x + threadIdx.x;
    if (i < MAX_ROWS) g_pair_token[i] = 0;
}

// Gating + fused w1/x fp16 conversion (independent work, overlapped blocks).
__global__ void gate_kernel(const float* __restrict__ x,
                            const float* __restrict__ gw,
                            const float4* __restrict__ w1src) {
    int b = blockIdx.x;
    if (b >= GATE_B) {
        int cb = b - GATE_B;
        if (cb < W1CONV_B) {                      // w1: 2048 blocks x 16384
            size_t base = (size_t)cb * 16384;
            uint2* dst = (uint2*)g_w1h;
            for (size_t i = base + threadIdx.x; i < base + 16384; i += 256)
                conv4(w1src, dst, i);
        } else {                                  // x: 256 blocks x 16384
            size_t base = (size_t)(cb - W1CONV_B) * 16384;
            const float4* xs = (const float4*)x;
            uint2* dst = (uint2*)g_xh;
            for (size_t i = base + threadIdx.x; i < base + 16384; i += 256)
                conv4(xs, dst, i);
        }
        return;
    }
    int gtid = b * blockDim.x + threadIdx.x;
    int t = gtid >> 5;
    int lane = gtid & 31;
    if (t >= BATCH) return;
    const float* xr = x + (size_t)t * DIN;
    float acc[NEXP];
#pragma unroll
    for (int e = 0; e < NEXP; e++) acc[e] = 0.0f;
    for (int k = lane; k < DIN; k += 32) {
        float xv = __ldg(xr + k);
#pragma unroll
        for (int e = 0; e < NEXP; e++) acc[e] += xv * __ldg(gw + e * DIN + k);
    }
#pragma unroll
    for (int off = 16; off > 0; off >>= 1) {
#pragma unroll
        for (int e = 0; e < NEXP; e++)
            acc[e] += __shfl_xor_sync(0xffffffffu, acc[e], off);
    }
    if (lane == 0) {
        float v0 = -1e30f, v1 = -1e30f;
        int i0 = 0, i1 = 0;
#pragma unroll
        for (int e = 0; e < NEXP; e++) {
            float v = acc[e];
            if (v > v0) { v1 = v0; i1 = i0; v0 = v; i0 = e; }
            else if (v > v1) { v1 = v; i1 = e; }
        }
        float e1 = expf(v1 - v0);
        float s = 1.0f + e1;
        g_tok_e[2 * t + 0] = i0;
        g_tok_e[2 * t + 1] = i1;
        g_tok_p[2 * t + 0] = 1.0f / s;
        g_tok_p[2 * t + 1] = e1 / s;
    }
}

__global__ void offsets_kernel() {
    __shared__ int cnt[NEXP];
    if (threadIdx.x < NEXP) cnt[threadIdx.x] = 0;
    __syncthreads();
    for (int t = threadIdx.x; t < BATCH; t += blockDim.x) {
        atomicAdd(&cnt[g_tok_e[2 * t + 0]], 1);
        atomicAdd(&cnt[g_tok_e[2 * t + 1]], 1);
    }
    __syncthreads();
    if (threadIdx.x == 0) {
        int off = 0;
        for (int e = 0; e < NEXP; e++) {
            g_offsets[e] = off;
            off += ((cnt[e] + BM - 1) / BM) * BM;
        }
        g_offsets[NEXP] = off;
    }
}

__global__ void assign_kernel() {
    int e = blockIdx.x;
    __shared__ int wcnt[8];
    __shared__ int sbase;
    if (threadIdx.x == 0) sbase = g_offsets[e];
    __syncthreads();
    int base = sbase;
    int lane = threadIdx.x & 31;
    int wid = threadIdx.x >> 5;
    for (int t0 = 0; t0 < BATCH; t0 += 256) {
        int t = t0 + threadIdx.x;
        int sel = 0, kk = 0;
        int e0 = g_tok_e[2 * t], e1 = g_tok_e[2 * t + 1];
        if (e0 == e)      { sel = 1; kk = 0; }
        else if (e1 == e) { sel = 1; kk = 1; }
        unsigned m = __ballot_sync(0xffffffffu, sel);
        if (lane == 0) wcnt[wid] = __popc(m);
        __syncthreads();
        int prefix = 0, tot = 0;
#pragma unroll
        for (int i = 0; i < 8; i++) {
            if (i < wid) prefix += wcnt[i];
            tot += wcnt[i];
        }
        if (sel) {
            int pos = base + prefix + __popc(m & ((1u << lane) - 1u));
            g_pair_token[pos] = t;
            g_tok_slot[2 * t + kk] = pos;
        }
        base += tot;
        __syncthreads();
    }
}

// out[t] = p0 * y[slot0] + p1 * y[slot1]  (covers every output element)
__global__ void combine_kernel(float* __restrict__ out) {
    int t = blockIdx.x;
    int s0 = g_tok_slot[2 * t], s1 = g_tok_slot[2 * t + 1];
    float p0 = g_tok_p[2 * t], p1 = g_tok_p[2 * t + 1];
    const float4* y0 = (const float4*)(g_y + (size_t)s0 * DOUT);
    const float4* y1 = (const float4*)(g_y + (size_t)s1 * DOUT);
    float4* o = (float4*)(out + (size_t)t * DOUT);
#pragma unroll
    for (int i = threadIdx.x; i < DOUT / 4; i += 256) {
        float4 a = y0[i], b = y1[i];
        o[i] = make_float4(p0 * a.x + p1 * b.x, p0 * a.y + p1 * b.y,
                           p0 * a.z + p1 * b.z, p0 * a.w + p1 * b.w);
    }
}

// ---------------------------------------------------------------------------
// Grouped GEMM: C[128x128] = A[128xK] * B[128xK]^T, fp16 HMMA.
// 4 warps, 2x2 warp grid, 64x64 warp tile, 2 CTAs/SM.
// P1: A = x fp16 (token gather), B = w1, epilogue gelu -> h fp16.
//     Extra grid.x rows (mt >= NMT) convert w2 fp32->fp16 (overlap).
// P2: A = h fp16 (slot rows), B = w2, epilogue plain stores -> g_y.
// ---------------------------------------------------------------------------
template <int KDIM, bool P1>
__global__ void __launch_bounds__(128, 2)
mma_gemm(const float* __restrict__ bias, const float4* __restrict__ wconv) {
    const int mt = P1 ? blockIdx.x : blockIdx.y;
    const int nt = P1 ? blockIdx.y : blockIdx.x;

    if (P1 && mt >= NMT) {            // fused w2 converter: 4096 blocks x 8192
        size_t base = ((size_t)(mt - NMT) * gridDim.y + blockIdx.y) * 8192;
        uint2* dst = (uint2*)g_w2h;
        for (size_t i = base + threadIdx.x; i < base + 8192; i += 128)
            conv4(wconv, dst, i);
        return;
    }

    __shared__ int s_off[NEXP + 1];
    __shared__ int stok[BM];
    __shared__ float sbias[BN];
    extern __shared__ char dsm[];

    const int tid = threadIdx.x;
    if (tid < NEXP + 1) s_off[tid] = g_offsets[tid];
    __syncthreads();
    const int row0 = mt * BM;
    if (row0 >= s_off[NEXP]) return;
    int e = 0;
    while (row0 >= s_off[e + 1]) e++;
    if (P1) stok[tid] = g_pair_token[row0 + tid];
    sbias[tid] = bias[(size_t)e * (P1 ? DHID : DOUT) + (size_t)nt * BN + tid];
    __syncthreads();

    const __half* Ag = P1 ? g_xh : g_hh;
    const __half* Bg = P1 ? g_w1h : g_w2h;

    uintptr_t pal = ((uintptr_t)dsm + 1023) & ~(uintptr_t)1023;
    const uint32_t su = smem_u32((void*)pal);

    // ---- producer mapping ----
    const int ch = tid & 7;
    const int rb = tid >> 3;
    const __half* aP[8];
    const size_t brow0 = (size_t)e * (P1 ? DHID : DOUT) + (size_t)nt * BN;
    const __half* bP0 = Bg + (brow0 + rb) * (size_t)KDIM + ch * 8;
#pragma unroll
    for (int i = 0; i < 8; i++) {
        int r = rb + i * 16;
        size_t ga = P1 ? (size_t)stok[r] * KDIM : (size_t)(row0 + r) * KDIM;
        aP[i] = Ag + ga + ch * 8;
    }
    const uint32_t swz0 = SWZ((uint32_t)rb * 128 + (uint32_t)ch * 16);

    auto issue = [&](int kt, int st) {
        uint32_t sb = su + st * STAGE_B;
        int ko = kt * 64;
#pragma unroll
        for (int i = 0; i < 8; i++)
            cp16(sb + A_O + swz0 + i * 2048, aP[i] + ko);
#pragma unroll
        for (int i = 0; i < 8; i++)
            cp16(sb + B_O + swz0 + i * 2048, bP0 + (size_t)i * 16 * KDIM + ko);
    };

    issue(0, 0);
    cp_commit();
    issue(1, 1);
    cp_commit();

    // ---- consumer mapping: 2x2 warp grid, warp tile 64x64 ----
    const int wid = tid >> 5, lane = tid & 31;
    const int warp_m = (wid >> 1) * 64;
    const int warp_n = (wid & 1) * 64;
    const uint32_t xorv = (uint32_t)(lane & 7) << 4;
    const uint32_t kx = (uint32_t)((lane >> 4) << 4);
    const uint32_t rowA =
        (uint32_t)(warp_m + (lane & 7) + ((lane >> 3) & 1) * 8) * 128;
    const uint32_t rowB =
        (uint32_t)(warp_n + (lane & 7) + ((lane >> 3) & 1) * 8) * 128;

    float acc[4][8][4];
#pragma unroll
    for (int i = 0; i < 4; i++)
#pragma unroll
        for (int j = 0; j < 8; j++)
#pragma unroll
            for (int q = 0; q < 4; q++) acc[i][j][q] = 0.0f;

    const int NCH = KDIM / 64;
#pragma unroll 1
    for (int c = 0; c < NCH; c++) {
        cp_wait<1>();
        __syncthreads();
        if (c + 2 < NCH) issue(c + 2, (c + 2) % 3);
        cp_commit();
        const uint32_t sb = su + (c % 3) * STAGE_B;
#pragma unroll
        for (int s = 0; s < 4; s++) {
            const uint32_t kt = (((uint32_t)(s * 32)) + kx) ^ xorv;
            uint32_t ah[4][4], bh[4][4];
#pragma unroll
            for (int mi = 0; mi < 4; mi++)
                ldsm4(ah[mi], sb + A_O + rowA + mi * 2048 + kt);
#pragma unroll
            for (int j = 0; j < 4; j++)
                ldsm4(bh[j], sb + B_O + rowB + j * 2048 + kt);
#pragma unroll
            for (int mi = 0; mi < 4; mi++)
#pragma unroll
                for (int nj = 0; nj < 8; nj++) {
                    uint32_t bhi[2] = {bh[nj >> 1][nj & 1], bh[nj >> 1][(nj & 1) + 2]};
                    mma16816(acc[mi][nj], ah[mi], bhi);
                }
        }
    }

    // ---- epilogue ----
    const int g = lane >> 2, t4 = lane & 3;
    if (P1) {
#pragma unroll
        for (int mi = 0; mi < 4; mi++) {
            int r0 = warp_m + mi * 16 + g;
#pragma unroll
            for (int nj = 0; nj < 8; nj++) {
                int cB = warp_n + nj * 8 + 2 * t4;
                float b0v = sbias[cB], b1v = sbias[cB + 1];
                float v00 = geluf(acc[mi][nj][0] + b0v);
                float v01 = geluf(acc[mi][nj][1] + b1v);
                float v10 = geluf(acc[mi][nj][2] + b0v);
                float v11 = geluf(acc[mi][nj][3] + b1v);
                size_t gc = (size_t)nt * BN + cB;
                __half2 p0 = __floats2half2_rn(v00, v01);
                __half2 p1 = __floats2half2_rn(v10, v11);
                *(uint32_t*)(g_hh + (size_t)(row0 + r0) * DHID + gc) =
                    *(uint32_t*)&p0;
                *(uint32_t*)(g_hh + (size_t)(row0 + r0 + 8) * DHID + gc) =
                    *(uint32_t*)&p1;
            }
        }
    } else {
#pragma unroll
        for (int mi = 0; mi < 4; mi++) {
            int r0 = warp_m + mi * 16 + g;
            float* y0 = g_y + (size_t)(row0 + r0) * DOUT + (size_t)nt * BN;
            float* y1 = g_y + (size_t)(row0 + r0 + 8) * DOUT + (size_t)nt * BN;
#pragma unroll
            for (int nj = 0; nj < 8; nj++) {
                int cB = warp_n + nj * 8 + 2 * t4;
                float b0v = sbias[cB], b1v = sbias[cB + 1];
                *(float2*)(y0 + cB) =
                    make_float2(acc[mi][nj][0] + b0v, acc[mi][nj][1] + b1v);
                *(float2*)(y1 + cB) =
                    make_float2(acc[mi][nj][2] + b0v, acc[mi][nj][3] + b1v);
            }
        }
    }
}

// ---------------------------------------------------------------------------
extern "C" void kernel_launch(void* const* d_in, const int* in_sizes, int n_in,
                              void* d_out, int out_size) {
    const float* x  = (const float*)d_in[0];
    const float* gw = (const float*)d_in[1];
    const float* w1 = (const float*)d_in[2];
    const float* b1 = (const float*)d_in[3];
    const float* w2 = (const float*)d_in[4];
    const float* b2 = (const float*)d_in[5];
    float* out = (float*)d_out;

    cudaFuncSetAttribute(mma_gemm<DIN, true>,
                         cudaFuncAttributeMaxDynamicSharedMemorySize, DYN_BYTES);
    cudaFuncSetAttribute(mma_gemm<DHID, false>,
                         cudaFuncAttributeMaxDynamicSharedMemorySize, DYN_BYTES);

    init_kernel<<<(MAX_ROWS + 255) / 256, 256>>>();
    gate_kernel<<<GATE_B + W1CONV_B + XCONV_B, 256>>>(x, gw, (const float4*)w1);
    offsets_kernel<<<1, 256>>>();
    assign_kernel<<<NEXP, 256>>>();

    mma_gemm<DIN, true><<<dim3(NMT + W2CONV_X, DHID / BN), 128, DYN_BYTES>>>(
        b1, (const float4*)w2);
    mma_gemm<DHID, false><<<dim3(DOUT / BN, NMT), 128, DYN_BYTES>>>(b2, nullptr);
    combine_kernel<<<BATCH, 256>>>(out);
}

// round 10
// speedup vs baseline: 1.0908x; 1.0085x over previous
#include <cuda_runtime.h>
#include <cuda_fp16.h>
#include <math.h>
#include <stdint.h>

// ---------------------------------------------------------------------------
// MoE top-2-of-8 via pure fp16 HMMA (fp32 accumulate).
// R10: (1) init+offsets+assign fused into one kernel (each expert block
// self-counts and zeroes its own padding); (2) mainloop fragment double-
// buffering: ldsm for s-iter s+1 issued before the 32 HMMAs of s, hiding
// LDS latency. GEMM geometry unchanged (128x128 CTA, 2x2 x 64x64, 2 CTA/SM).
// ---------------------------------------------------------------------------

#define BATCH 8192
#define NEXP  8
#define DIN   2048
#define DHID  8192
#define DOUT  2048

#define BM 128
#define BN 128
#define MAX_ROWS 17408
#define NMT (MAX_ROWS / BM)

#define A_O 0
#define B_O 16384
#define STAGE_B 32768
#define DYN_BYTES (3 * STAGE_B + 1024)

#define GATE_B 1024
#define W1CONV_B 2048
#define XCONV_B 256
#define W2CONV_X 64

#define SWZ(o) ((o) ^ (((o) >> 3) & 0x70))

// ---- device scratch --------------------------------------------------------
__device__ __half g_w1h[(size_t)NEXP * DHID * DIN];
__device__ __half g_w2h[(size_t)NEXP * DOUT * DHID];
__device__ __half g_xh[(size_t)BATCH * DIN];
__device__ __half g_hh[(size_t)MAX_ROWS * DHID];
__device__ float  g_y[(size_t)MAX_ROWS * DOUT];

__device__ int   g_tok_e[BATCH * 2];
__device__ float g_tok_p[BATCH * 2];
__device__ int   g_tok_slot[BATCH * 2];
__device__ int   g_pair_token[MAX_ROWS];
__device__ int   g_offsets[NEXP + 1];

// ---- helpers ----------------------------------------------------------------
__device__ __forceinline__ uint32_t smem_u32(const void* p) {
    uint32_t a;
    asm("{ .reg .u64 t; cvta.to.shared.u64 t, %1; cvt.u32.u64 %0, t; }"
        : "=r"(a) : "l"(p));
    return a;
}
__device__ __forceinline__ void cp16(uint32_t s, const void* g) {
    asm volatile("cp.async.cg.shared.global [%0], [%1], 16;" :: "r"(s), "l"(g));
}
__device__ __forceinline__ void cp_commit() {
    asm volatile("cp.async.commit_group;" ::: "memory");
}
template <int N>
__device__ __forceinline__ void cp_wait() {
    asm volatile("cp.async.wait_group %0;" :: "n"(N) : "memory");
}
__device__ __forceinline__ void ldsm4(uint32_t* r, uint32_t addr) {
    asm volatile("ldmatrix.sync.aligned.m8n8.x4.shared.b16 {%0,%1,%2,%3}, [%4];"
                 : "=r"(r[0]), "=r"(r[1]), "=r"(r[2]), "=r"(r[3]) : "r"(addr));
}
__device__ __forceinline__ void mma16816(float* d, const uint32_t* a,
                                         const uint32_t* b) {
    asm volatile(
        "mma.sync.aligned.m16n8k16.row.col.f32.f16.f16.f32 "
        "{%0,%1,%2,%3}, {%4,%5,%6,%7}, {%8,%9}, {%0,%1,%2,%3};"
        : "+f"(d[0]), "+f"(d[1]), "+f"(d[2]), "+f"(d[3])
        : "r"(a[0]), "r"(a[1]), "r"(a[2]), "r"(a[3]), "r"(b[0]), "r"(b[1]));
}
__device__ __forceinline__ float geluf(float v) {
    return 0.5f * v * (1.0f + erff(v * 0.7071067811865476f));
}
__device__ __forceinline__ void conv4(const float4* __restrict__ src,
                                      uint2* __restrict__ dst, size_t i) {
    float4 v = src[i];
    __half2 h0 = __floats2half2_rn(v.x, v.y);
    __half2 h1 = __floats2half2_rn(v.z, v.w);
    dst[i] = make_uint2(*(uint32_t*)&h0, *(uint32_t*)&h1);
}

// ---------------------------------------------------------------------------
// Gating + fused w1/x fp16 conversion.
__global__ void gate_kernel(const float* __restrict__ x,
                            const float* __restrict__ gw,
                            const float4* __restrict__ w1src) {
    int b = blockIdx.x;
    if (b >= GATE_B) {
        int cb = b - GATE_B;
        if (cb < W1CONV_B) {
            size_t base = (size_t)cb * 16384;
            uint2* dst = (uint2*)g_w1h;
            for (size_t i = base + threadIdx.x; i < base + 16384; i += 256)
                conv4(w1src, dst, i);
        } else {
            size_t base = (size_t)(cb - W1CONV_B) * 16384;
            const float4* xs = (const float4*)x;
            uint2* dst = (uint2*)g_xh;
            for (size_t i = base + threadIdx.x; i < base + 16384; i += 256)
                conv4(xs, dst, i);
        }
        return;
    }
    int gtid = b * blockDim.x + threadIdx.x;
    int t = gtid >> 5;
    int lane = gtid & 31;
    if (t >= BATCH) return;
    const float* xr = x + (size_t)t * DIN;
    float acc[NEXP];
#pragma unroll
    for (int e = 0; e < NEXP; e++) acc[e] = 0.0f;
    for (int k = lane; k < DIN; k += 32) {
        float xv = __ldg(xr + k);
#pragma unroll
        for (int e = 0; e < NEXP; e++) acc[e] += xv * __ldg(gw + e * DIN + k);
    }
#pragma unroll
    for (int off = 16; off > 0; off >>= 1) {
#pragma unroll
        for (int e = 0; e < NEXP; e++)
            acc[e] += __shfl_xor_sync(0xffffffffu, acc[e], off);
    }
    if (lane == 0) {
        float v0 = -1e30f, v1 = -1e30f;
        int i0 = 0, i1 = 0;
#pragma unroll
        for (int e = 0; e < NEXP; e++) {
            float v = acc[e];
            if (v > v0) { v1 = v0; i1 = i0; v0 = v; i0 = e; }
            else if (v > v1) { v1 = v; i1 = e; }
        }
        float e1 = expf(v1 - v0);
        float s = 1.0f + e1;
        g_tok_e[2 * t + 0] = i0;
        g_tok_e[2 * t + 1] = i1;
        g_tok_p[2 * t + 0] = 1.0f / s;
        g_tok_p[2 * t + 1] = e1 / s;
    }
}

// Fused: per-expert block counts ALL experts itself, derives its padded base,
// compacts its tokens in order, zeroes its own padding slots.
// Block 0 additionally publishes g_offsets.
__global__ void assign_kernel() {
    int e = blockIdx.x;
    __shared__ int cnt[NEXP];
    __shared__ int wcnt[8];
    if (threadIdx.x < NEXP) cnt[threadIdx.x] = 0;
    __syncthreads();
    for (int t = threadIdx.x; t < BATCH; t += 256) {
        atomicAdd(&cnt[g_tok_e[2 * t + 0]], 1);
        atomicAdd(&cnt[g_tok_e[2 * t + 1]], 1);
    }
    __syncthreads();
    int base = 0;
    for (int i = 0; i < e; i++) base += ((cnt[i] + BM - 1) / BM) * BM;
    const int my_cnt = cnt[e];
    const int my_pad = ((my_cnt + BM - 1) / BM) * BM;
    if (e == 0 && threadIdx.x == 0) {
        int off = 0;
        for (int i = 0; i < NEXP; i++) {
            g_offsets[i] = off;
            off += ((cnt[i] + BM - 1) / BM) * BM;
        }
        g_offsets[NEXP] = off;
    }
    // zero padding slots of my segment
    for (int i = base + my_cnt + threadIdx.x; i < base + my_pad; i += 256)
        g_pair_token[i] = 0;

    int lane = threadIdx.x & 31;
    int wid = threadIdx.x >> 5;
    int run = base;
    for (int t0 = 0; t0 < BATCH; t0 += 256) {
        int t = t0 + threadIdx.x;
        int sel = 0, kk = 0;
        int e0 = g_tok_e[2 * t], e1 = g_tok_e[2 * t + 1];
        if (e0 == e)      { sel = 1; kk = 0; }
        else if (e1 == e) { sel = 1; kk = 1; }
        unsigned m = __ballot_sync(0xffffffffu, sel);
        if (lane == 0) wcnt[wid] = __popc(m);
        __syncthreads();
        int prefix = 0, tot = 0;
#pragma unroll
        for (int i = 0; i < 8; i++) {
            if (i < wid) prefix += wcnt[i];
            tot += wcnt[i];
        }
        if (sel) {
            int pos = run + prefix + __popc(m & ((1u << lane) - 1u));
            g_pair_token[pos] = t;
            g_tok_slot[2 * t + kk] = pos;
        }
        run += tot;
        __syncthreads();
    }
}

// out[t] = p0 * y[slot0] + p1 * y[slot1]
__global__ void combine_kernel(float* __restrict__ out) {
    int t = blockIdx.x;
    int s0 = g_tok_slot[2 * t], s1 = g_tok_slot[2 * t + 1];
    float p0 = g_tok_p[2 * t], p1 = g_tok_p[2 * t + 1];
    const float4* y0 = (const float4*)(g_y + (size_t)s0 * DOUT);
    const float4* y1 = (const float4*)(g_y + (size_t)s1 * DOUT);
    float4* o = (float4*)(out + (size_t)t * DOUT);
#pragma unroll
    for (int i = threadIdx.x; i < DOUT / 4; i += 256) {
        float4 a = y0[i], b = y1[i];
        o[i] = make_float4(p0 * a.x + p1 * b.x, p0 * a.y + p1 * b.y,
                           p0 * a.z + p1 * b.z, p0 * a.w + p1 * b.w);
    }
}

// ---------------------------------------------------------------------------
// Grouped GEMM: C[128x128] = A[128xK] * B[128xK]^T, fp16 HMMA.
// 4 warps, 2x2 warp grid, 64x64 warp tile, 2 CTAs/SM.
// In-chunk fragment double-buffering: ldsm(s+1) issued before MMA(s).
// ---------------------------------------------------------------------------
template <int KDIM, bool P1>
__global__ void __launch_bounds__(128, 2)
mma_gemm(const float* __restrict__ bias, const float4* __restrict__ wconv) {
    const int mt = P1 ? blockIdx.x : blockIdx.y;
    const int nt = P1 ? blockIdx.y : blockIdx.x;

    if (P1 && mt >= NMT) {            // fused w2 converter
        size_t base = ((size_t)(mt - NMT) * gridDim.y + blockIdx.y) * 8192;
        uint2* dst = (uint2*)g_w2h;
        for (size_t i = base + threadIdx.x; i < base + 8192; i += 128)
            conv4(wconv, dst, i);
        return;
    }

    __shared__ int s_off[NEXP + 1];
    __shared__ int stok[BM];
    __shared__ float sbias[BN];
    extern __shared__ char dsm[];

    const int tid = threadIdx.x;
    if (tid < NEXP + 1) s_off[tid] = g_offsets[tid];
    __syncthreads();
    const int row0 = mt * BM;
    if (row0 >= s_off[NEXP]) return;
    int e = 0;
    while (row0 >= s_off[e + 1]) e++;
    if (P1) stok[tid] = g_pair_token[row0 + tid];
    sbias[tid] = bias[(size_t)e * (P1 ? DHID : DOUT) + (size_t)nt * BN + tid];
    __syncthreads();

    const __half* Ag = P1 ? g_xh : g_hh;
    const __half* Bg = P1 ? g_w1h : g_w2h;

    uintptr_t pal = ((uintptr_t)dsm + 1023) & ~(uintptr_t)1023;
    const uint32_t su = smem_u32((void*)pal);

    // ---- producer mapping ----
    const int ch = tid & 7;
    const int rb = tid >> 3;
    uint32_t aOff[8];                  // byte offsets into Ag (u32: <=64MB)
    const size_t brow0 = (size_t)e * (P1 ? DHID : DOUT) + (size_t)nt * BN;
    const __half* bP0 = Bg + (brow0 + rb) * (size_t)KDIM + ch * 8;
#pragma unroll
    for (int i = 0; i < 8; i++) {
        int r = rb + i * 16;
        size_t ga = P1 ? (size_t)stok[r] * KDIM : (size_t)(row0 + r) * KDIM;
        aOff[i] = (uint32_t)((ga + ch * 8) * 2);
    }
    const uint32_t swz0 = SWZ((uint32_t)rb * 128 + (uint32_t)ch * 16);
    const char* Agb = (const char*)Ag;

    auto issue = [&](int kt, int st) {
        uint32_t sb = su + st * STAGE_B;
        uint32_t ko = (uint32_t)kt * 128;   // bytes
#pragma unroll
        for (int i = 0; i < 8; i++)
            cp16(sb + A_O + swz0 + i * 2048, Agb + aOff[i] + ko);
#pragma unroll
        for (int i = 0; i < 8; i++)
            cp16(sb + B_O + swz0 + i * 2048,
                 bP0 + (size_t)i * 16 * KDIM + kt * 64);
    };

    issue(0, 0);
    cp_commit();
    issue(1, 1);
    cp_commit();

    // ---- consumer mapping ----
    const int wid = tid >> 5, lane = tid & 31;
    const int warp_m = (wid >> 1) * 64;
    const int warp_n = (wid & 1) * 64;
    const uint32_t xorv = (uint32_t)(lane & 7) << 4;
    const uint32_t kx = (uint32_t)((lane >> 4) << 4);
    const uint32_t rowA =
        (uint32_t)(warp_m + (lane & 7) + ((lane >> 3) & 1) * 8) * 128;
    const uint32_t rowB =
        (uint32_t)(warp_n + (lane & 7) + ((lane >> 3) & 1) * 8) * 128;

    float acc[4][8][4];
#pragma unroll
    for (int i = 0; i < 4; i++)
#pragma unroll
        for (int j = 0; j < 8; j++)
#pragma unroll
            for (int q = 0; q < 4; q++) acc[i][j][q] = 0.0f;

    uint32_t ah[2][4][4], bh[2][4][4];

    auto load_frags = [&](uint32_t sb, int s, int buf) {
        const uint32_t kt = (((uint32_t)(s * 32)) + kx) ^ xorv;
#pragma unroll
        for (int mi = 0; mi < 4; mi++)
            ldsm4(ah[buf][mi], sb + A_O + rowA + mi * 2048 + kt);
#pragma unroll
        for (int j = 0; j < 4; j++)
            ldsm4(bh[buf][j], sb + B_O + rowB + j * 2048 + kt);
    };

    const int NCH = KDIM / 64;
#pragma unroll 1
    for (int c = 0; c < NCH; c++) {
        cp_wait<1>();
        __syncthreads();
        if (c + 2 < NCH) issue(c + 2, (c + 2) % 3);
        cp_commit();
        const uint32_t sb = su + (c % 3) * STAGE_B;
        load_frags(sb, 0, 0);
#pragma unroll
        for (int s = 0; s < 4; s++) {
            const int cur = s & 1;
            if (s < 3) load_frags(sb, s + 1, cur ^ 1);
#pragma unroll
            for (int mi = 0; mi < 4; mi++)
#pragma unroll
                for (int nj = 0; nj < 8; nj++) {
                    uint32_t bhi[2] = {bh[cur][nj >> 1][nj & 1],
                                       bh[cur][nj >> 1][(nj & 1) + 2]};
                    mma16816(acc[mi][nj], ah[cur][mi], bhi);
                }
        }
    }

    // ---- epilogue ----
    const int g = lane >> 2, t4 = lane & 3;
    if (P1) {
#pragma unroll
        for (int mi = 0; mi < 4; mi++) {
            int r0 = warp_m + mi * 16 + g;
#pragma unroll
            for (int nj = 0; nj < 8; nj++) {
                int cB = warp_n + nj * 8 + 2 * t4;
                float b0v = sbias[cB], b1v = sbias[cB + 1];
                float v00 = geluf(acc[mi][nj][0] + b0v);
                float v01 = geluf(acc[mi][nj][1] + b1v);
                float v10 = geluf(acc[mi][nj][2] + b0v);
                float v11 = geluf(acc[mi][nj][3] + b1v);
                size_t gc = (size_t)nt * BN + cB;
                __half2 p0 = __floats2half2_rn(v00, v01);
                __half2 p1 = __floats2half2_rn(v10, v11);
                *(uint32_t*)(g_hh + (size_t)(row0 + r0) * DHID + gc) =
                    *(uint32_t*)&p0;
                *(uint32_t*)(g_hh + (size_t)(row0 + r0 + 8) * DHID + gc) =
                    *(uint32_t*)&p1;
            }
        }
    } else {
#pragma unroll
        for (int mi = 0; mi < 4; mi++) {
            int r0 = warp_m + mi * 16 + g;
            float* y0 = g_y + (size_t)(row0 + r0) * DOUT + (size_t)nt * BN;
            float* y1 = g_y + (size_t)(row0 + r0 + 8) * DOUT + (size_t)nt * BN;
#pragma unroll
            for (int nj = 0; nj < 8; nj++) {
                int cB = warp_n + nj * 8 + 2 * t4;
                float b0v = sbias[cB], b1v = sbias[cB + 1];
                *(float2*)(y0 + cB) =
                    make_float2(acc[mi][nj][0] + b0v, acc[mi][nj][1] + b1v);
                *(float2*)(y1 + cB) =
                    make_float2(acc[mi][nj][2] + b0v, acc[mi][nj][3] + b1v);
            }
        }
    }
}

// ---------------------------------------------------------------------------
extern "C" void kernel_launch(void* const* d_in, const int* in_sizes, int n_in,
                              void* d_out, int out_size) {
    const float* x  = (const float*)d_in[0];
    const float* gw = (const float*)d_in[1];
    const float* w1 = (const float*)d_in[2];
    const float* b1 = (const float*)d_in[3];
    const float* w2 = (const float*)d_in[4];
    const float* b2 = (const float*)d_in[5];
    float* out = (float*)d_out;

    cudaFuncSetAttribute(mma_gemm<DIN, true>,
                         cudaFuncAttributeMaxDynamicSharedMemorySize, DYN_BYTES);
    cudaFuncSetAttribute(mma_gemm<DHID, false>,
                         cudaFuncAttributeMaxDynamicSharedMemorySize, DYN_BYTES);

    gate_kernel<<<GATE_B + W1CONV_B + XCONV_B, 256>>>(x, gw, (const float4*)w1);
    assign_kernel<<<NEXP, 256>>>();

    mma_gemm<DIN, true><<<dim3(NMT + W2CONV_X, DHID / BN), 128, DYN_BYTES>>>(
        b1, (const float4*)w2);
    mma_gemm<DHID, false><<<dim3(DOUT / BN, NMT), 128, DYN_BYTES>>>(b2, nullptr);
    combine_kernel<<<BATCH, 256>>>(out);
}

// round 11
// speedup vs baseline: 1.2614x; 1.1564x over previous
#include <cuda_runtime.h>
#include <cuda_fp16.h>
#include <math.h>
#include <stdint.h>

// ---------------------------------------------------------------------------
// MoE top-2-of-8 via pure fp16 HMMA (fp32 accumulate).
// R11: B-fragment ldmatrix lane mapping reordered (bit3<->bit4) so each
// mma16816's B operand is an adjacent register pair -> removes ~2 MOV/MMA
// marshaling (ncu R10: alu=20% of issue, tensor stuck at 67%).
// Geometry unchanged: 128x128 CTA, 2x2 warps of 64x64, 3-stage cp.async,
// 2 CTAs/SM; fused converters; slot-indexed pass2 + combine.
// ---------------------------------------------------------------------------

#define BATCH 8192
#define NEXP  8
#define DIN   2048
#define DHID  8192
#define DOUT  2048

#define BM 128
#define BN 128
#define MAX_ROWS 17408
#define NMT (MAX_ROWS / BM)

#define A_O 0
#define B_O 16384
#define STAGE_B 32768
#define DYN_BYTES (3 * STAGE_B + 1024)

#define GATE_B 1024
#define W1CONV_B 2048
#define XCONV_B 256
#define W2CONV_X 64

#define SWZ(o) ((o) ^ (((o) >> 3) & 0x70))

// ---- device scratch --------------------------------------------------------
__device__ __half g_w1h[(size_t)NEXP * DHID * DIN];
__device__ __half g_w2h[(size_t)NEXP * DOUT * DHID];
__device__ __half g_xh[(size_t)BATCH * DIN];
__device__ __half g_hh[(size_t)MAX_ROWS * DHID];
__device__ float  g_y[(size_t)MAX_ROWS * DOUT];

__device__ int   g_tok_e[BATCH * 2];
__device__ float g_tok_p[BATCH * 2];
__device__ int   g_tok_slot[BATCH * 2];
__device__ int   g_pair_token[MAX_ROWS];
__device__ int   g_offsets[NEXP + 1];

// ---- helpers ----------------------------------------------------------------
__device__ __forceinline__ uint32_t smem_u32(const void* p) {
    uint32_t a;
    asm("{ .reg .u64 t; cvta.to.shared.u64 t, %1; cvt.u32.u64 %0, t; }"
        : "=r"(a) : "l"(p));
    return a;
}
__device__ __forceinline__ void cp16(uint32_t s, const void* g) {
    asm volatile("cp.async.cg.shared.global [%0], [%1], 16;" :: "r"(s), "l"(g));
}
__device__ __forceinline__ void cp_commit() {
    asm volatile("cp.async.commit_group;" ::: "memory");
}
template <int N>
__device__ __forceinline__ void cp_wait() {
    asm volatile("cp.async.wait_group %0;" :: "n"(N) : "memory");
}
__device__ __forceinline__ void ldsm4(uint32_t* r, uint32_t addr) {
    asm volatile("ldmatrix.sync.aligned.m8n8.x4.shared.b16 {%0,%1,%2,%3}, [%4];"
                 : "=r"(r[0]), "=r"(r[1]), "=r"(r[2]), "=r"(r[3]) : "r"(addr));
}
__device__ __forceinline__ void mma16816(float* d, const uint32_t* a,
                                         const uint32_t* b) {
    asm volatile(
        "mma.sync.aligned.m16n8k16.row.col.f32.f16.f16.f32 "
        "{%0,%1,%2,%3}, {%4,%5,%6,%7}, {%8,%9}, {%0,%1,%2,%3};"
        : "+f"(d[0]), "+f"(d[1]), "+f"(d[2]), "+f"(d[3])
        : "r"(a[0]), "r"(a[1]), "r"(a[2]), "r"(a[3]), "r"(b[0]), "r"(b[1]));
}
__device__ __forceinline__ float geluf(float v) {
    return 0.5f * v * (1.0f + erff(v * 0.7071067811865476f));
}
__device__ __forceinline__ void conv4(const float4* __restrict__ src,
                                      uint2* __restrict__ dst, size_t i) {
    float4 v = src[i];
    __half2 h0 = __floats2half2_rn(v.x, v.y);
    __half2 h1 = __floats2half2_rn(v.z, v.w);
    dst[i] = make_uint2(*(uint32_t*)&h0, *(uint32_t*)&h1);
}

// ---------------------------------------------------------------------------
// Gating + fused w1/x fp16 conversion.
__global__ void gate_kernel(const float* __restrict__ x,
                            const float* __restrict__ gw,
                            const float4* __restrict__ w1src) {
    int b = blockIdx.x;
    if (b >= GATE_B) {
        int cb = b - GATE_B;
        if (cb < W1CONV_B) {
            size_t base = (size_t)cb * 16384;
            uint2* dst = (uint2*)g_w1h;
            for (size_t i = base + threadIdx.x; i < base + 16384; i += 256)
                conv4(w1src, dst, i);
        } else {
            size_t base = (size_t)(cb - W1CONV_B) * 16384;
            const float4* xs = (const float4*)x;
            uint2* dst = (uint2*)g_xh;
            for (size_t i = base + threadIdx.x; i < base + 16384; i += 256)
                conv4(xs, dst, i);
        }
        return;
    }
    int gtid = b * blockDim.x + threadIdx.x;
    int t = gtid >> 5;
    int lane = gtid & 31;
    if (t >= BATCH) return;
    const float* xr = x + (size_t)t * DIN;
    float acc[NEXP];
#pragma unroll
    for (int e = 0; e < NEXP; e++) acc[e] = 0.0f;
    for (int k = lane; k < DIN; k += 32) {
        float xv = __ldg(xr + k);
#pragma unroll
        for (int e = 0; e < NEXP; e++) acc[e] += xv * __ldg(gw + e * DIN + k);
    }
#pragma unroll
    for (int off = 16; off > 0; off >>= 1) {
#pragma unroll
        for (int e = 0; e < NEXP; e++)
            acc[e] += __shfl_xor_sync(0xffffffffu, acc[e], off);
    }
    if (lane == 0) {
        float v0 = -1e30f, v1 = -1e30f;
        int i0 = 0, i1 = 0;
#pragma unroll
        for (int e = 0; e < NEXP; e++) {
            float v = acc[e];
            if (v > v0) { v1 = v0; i1 = i0; v0 = v; i0 = e; }
            else if (v > v1) { v1 = v; i1 = e; }
        }
        float e1 = expf(v1 - v0);
        float s = 1.0f + e1;
        g_tok_e[2 * t + 0] = i0;
        g_tok_e[2 * t + 1] = i1;
        g_tok_p[2 * t + 0] = 1.0f / s;
        g_tok_p[2 * t + 1] = e1 / s;
    }
}

// Fused counts + offsets + ordered compaction + padding zero.
__global__ void assign_kernel() {
    int e = blockIdx.x;
    __shared__ int cnt[NEXP];
    __shared__ int wcnt[8];
    if (threadIdx.x < NEXP) cnt[threadIdx.x] = 0;
    __syncthreads();
    for (int t = threadIdx.x; t < BATCH; t += 256) {
        atomicAdd(&cnt[g_tok_e[2 * t + 0]], 1);
        atomicAdd(&cnt[g_tok_e[2 * t + 1]], 1);
    }
    __syncthreads();
    int base = 0;
    for (int i = 0; i < e; i++) base += ((cnt[i] + BM - 1) / BM) * BM;
    const int my_cnt = cnt[e];
    const int my_pad = ((my_cnt + BM - 1) / BM) * BM;
    if (e == 0 && threadIdx.x == 0) {
        int off = 0;
        for (int i = 0; i < NEXP; i++) {
            g_offsets[i] = off;
            off += ((cnt[i] + BM - 1) / BM) * BM;
        }
        g_offsets[NEXP] = off;
    }
    for (int i = base + my_cnt + threadIdx.x; i < base + my_pad; i += 256)
        g_pair_token[i] = 0;

    int lane = threadIdx.x & 31;
    int wid = threadIdx.x >> 5;
    int run = base;
    for (int t0 = 0; t0 < BATCH; t0 += 256) {
        int t = t0 + threadIdx.x;
        int sel = 0, kk = 0;
        int e0 = g_tok_e[2 * t], e1 = g_tok_e[2 * t + 1];
        if (e0 == e)      { sel = 1; kk = 0; }
        else if (e1 == e) { sel = 1; kk = 1; }
        unsigned m = __ballot_sync(0xffffffffu, sel);
        if (lane == 0) wcnt[wid] = __popc(m);
        __syncthreads();
        int prefix = 0, tot = 0;
#pragma unroll
        for (int i = 0; i < 8; i++) {
            if (i < wid) prefix += wcnt[i];
            tot += wcnt[i];
        }
        if (sel) {
            int pos = run + prefix + __popc(m & ((1u << lane) - 1u));
            g_pair_token[pos] = t;
            g_tok_slot[2 * t + kk] = pos;
        }
        run += tot;
        __syncthreads();
    }
}

// out[t] = p0 * y[slot0] + p1 * y[slot1]
__global__ void combine_kernel(float* __restrict__ out) {
    int t = blockIdx.x;
    int s0 = g_tok_slot[2 * t], s1 = g_tok_slot[2 * t + 1];
    float p0 = g_tok_p[2 * t], p1 = g_tok_p[2 * t + 1];
    const float4* y0 = (const float4*)(g_y + (size_t)s0 * DOUT);
    const float4* y1 = (const float4*)(g_y + (size_t)s1 * DOUT);
    float4* o = (float4*)(out + (size_t)t * DOUT);
#pragma unroll
    for (int i = threadIdx.x; i < DOUT / 4; i += 256) {
        float4 a = y0[i], b = y1[i];
        o[i] = make_float4(p0 * a.x + p1 * b.x, p0 * a.y + p1 * b.y,
                           p0 * a.z + p1 * b.z, p0 * a.w + p1 * b.w);
    }
}

// ---------------------------------------------------------------------------
// Grouped GEMM: C[128x128] = A[128xK] * B[128xK]^T, fp16 HMMA.
// 4 warps, 2x2 warp grid, 64x64 warp tile, 2 CTAs/SM, frag double-buffer.
// B ldmatrix mapping: bit4 selects n8-block, bit3 selects k-half, so each
// n8 block's (k-lo, k-hi) fragments are ADJACENT ldsm4 outputs.
// ---------------------------------------------------------------------------
template <int KDIM, bool P1>
__global__ void __launch_bounds__(128, 2)
mma_gemm(const float* __restrict__ bias, const float4* __restrict__ wconv) {
    const int mt = P1 ? blockIdx.x : blockIdx.y;
    const int nt = P1 ? blockIdx.y : blockIdx.x;

    if (P1 && mt >= NMT) {            // fused w2 converter
        size_t base = ((size_t)(mt - NMT) * gridDim.y + blockIdx.y) * 8192;
        uint2* dst = (uint2*)g_w2h;
        for (size_t i = base + threadIdx.x; i < base + 8192; i += 128)
            conv4(wconv, dst, i);
        return;
    }

    __shared__ int s_off[NEXP + 1];
    __shared__ int stok[BM];
    __shared__ float sbias[BN];
    extern __shared__ char dsm[];

    const int tid = threadIdx.x;
    if (tid < NEXP + 1) s_off[tid] = g_offsets[tid];
    __syncthreads();
    const int row0 = mt * BM;
    if (row0 >= s_off[NEXP]) return;
    int e = 0;
    while (row0 >= s_off[e + 1]) e++;
    if (P1) stok[tid] = g_pair_token[row0 + tid];
    sbias[tid] = bias[(size_t)e * (P1 ? DHID : DOUT) + (size_t)nt * BN + tid];
    __syncthreads();

    const __half* Ag = P1 ? g_xh : g_hh;
    const __half* Bg = P1 ? g_w1h : g_w2h;

    uintptr_t pal = ((uintptr_t)dsm + 1023) & ~(uintptr_t)1023;
    const uint32_t su = smem_u32((void*)pal);

    // ---- producer mapping ----
    const int ch = tid & 7;
    const int rb = tid >> 3;
    uint32_t aOff[8];
    const size_t brow0 = (size_t)e * (P1 ? DHID : DOUT) + (size_t)nt * BN;
    const __half* bP0 = Bg + (brow0 + rb) * (size_t)KDIM + ch * 8;
#pragma unroll
    for (int i = 0; i < 8; i++) {
        int r = rb + i * 16;
        size_t ga = P1 ? (size_t)stok[r] * KDIM : (size_t)(row0 + r) * KDIM;
        aOff[i] = (uint32_t)((ga + ch * 8) * 2);
    }
    const uint32_t swz0 = SWZ((uint32_t)rb * 128 + (uint32_t)ch * 16);
    const char* Agb = (const char*)Ag;

    auto issue = [&](int kt, int st) {
        uint32_t sb = su + st * STAGE_B;
        uint32_t ko = (uint32_t)kt * 128;
#pragma unroll
        for (int i = 0; i < 8; i++)
            cp16(sb + A_O + swz0 + i * 2048, Agb + aOff[i] + ko);
#pragma unroll
        for (int i = 0; i < 8; i++)
            cp16(sb + B_O + swz0 + i * 2048,
                 bP0 + (size_t)i * 16 * KDIM + kt * 64);
    };

    issue(0, 0);
    cp_commit();
    issue(1, 1);
    cp_commit();

    // ---- consumer mapping ----
    const int wid = tid >> 5, lane = tid & 31;
    const int warp_m = (wid >> 1) * 64;
    const int warp_n = (wid & 1) * 64;
    const uint32_t xorv = (uint32_t)(lane & 7) << 4;
    // A: bit3 -> +8 rows, bit4 -> k-half (fragment order a0,a1 rows / a2,a3 k-hi)
    const uint32_t kxA = (uint32_t)((lane >> 4) << 4);
    const uint32_t rowA =
        (uint32_t)(warp_m + (lane & 7) + ((lane >> 3) & 1) * 8) * 128;
    // B: bit4 -> +8 rows, bit3 -> k-half (fragments (r0,r1)=n-block lo, (r2,r3)=hi)
    const uint32_t kxB = (uint32_t)(((lane >> 3) & 1) << 4);
    const uint32_t rowB =
        (uint32_t)(warp_n + (lane & 7) + ((lane >> 4) & 1) * 8) * 128;

    float acc[4][8][4];
#pragma unroll
    for (int i = 0; i < 4; i++)
#pragma unroll
        for (int j = 0; j < 8; j++)
#pragma unroll
            for (int q = 0; q < 4; q++) acc[i][j][q] = 0.0f;

    uint32_t ah[2][4][4], bh[2][4][4];

    auto load_frags = [&](uint32_t sb, int s, int buf) {
        const uint32_t ktA = (((uint32_t)(s * 32)) + kxA) ^ xorv;
        const uint32_t ktB = (((uint32_t)(s * 32)) + kxB) ^ xorv;
#pragma unroll
        for (int mi = 0; mi < 4; mi++)
            ldsm4(ah[buf][mi], sb + A_O + rowA + mi * 2048 + ktA);
#pragma unroll
        for (int j = 0; j < 4; j++)
            ldsm4(bh[buf][j], sb + B_O + rowB + j * 2048 + ktB);
    };

    const int NCH = KDIM / 64;
#pragma unroll 1
    for (int c = 0; c < NCH; c++) {
        cp_wait<1>();
        __syncthreads();
        if (c + 2 < NCH) issue(c + 2, (c + 2) % 3);
        cp_commit();
        const uint32_t sb = su + (c % 3) * STAGE_B;
        load_frags(sb, 0, 0);
#pragma unroll
        for (int s = 0; s < 4; s++) {
            const int cur = s & 1;
            if (s < 3) load_frags(sb, s + 1, cur ^ 1);
#pragma unroll
            for (int mi = 0; mi < 4; mi++)
#pragma unroll
                for (int nj = 0; nj < 8; nj++)
                    mma16816(acc[mi][nj], ah[cur][mi],
                             &bh[cur][nj >> 1][(nj & 1) * 2]);
        }
    }

    // ---- epilogue ----
    const int g = lane >> 2, t4 = lane & 3;
    if (P1) {
#pragma unroll
        for (int mi = 0; mi < 4; mi++) {
            int r0 = warp_m + mi * 16 + g;
#pragma unroll
            for (int nj = 0; nj < 8; nj++) {
                int cB = warp_n + nj * 8 + 2 * t4;
                float b0v = sbias[cB], b1v = sbias[cB + 1];
                float v00 = geluf(acc[mi][nj][0] + b0v);
                float v01 = geluf(acc[mi][nj][1] + b1v);
                float v10 = geluf(acc[mi][nj][2] + b0v);
                float v11 = geluf(acc[mi][nj][3] + b1v);
                size_t gc = (size_t)nt * BN + cB;
                __half2 p0 = __floats2half2_rn(v00, v01);
                __half2 p1 = __floats2half2_rn(v10, v11);
                *(uint32_t*)(g_hh + (size_t)(row0 + r0) * DHID + gc) =
                    *(uint32_t*)&p0;
                *(uint32_t*)(g_hh + (size_t)(row0 + r0 + 8) * DHID + gc) =
                    *(uint32_t*)&p1;
            }
        }
    } else {
#pragma unroll
        for (int mi = 0; mi < 4; mi++) {
            int r0 = warp_m + mi * 16 + g;
            float* y0 = g_y + (size_t)(row0 + r0) * DOUT + (size_t)nt * BN;
            float* y1 = g_y + (size_t)(row0 + r0 + 8) * DOUT + (size_t)nt * BN;
#pragma unroll
            for (int nj = 0; nj < 8; nj++) {
                int cB = warp_n + nj * 8 + 2 * t4;
                float b0v = sbias[cB], b1v = sbias[cB + 1];
                *(float2*)(y0 + cB) =
                    make_float2(acc[mi][nj][0] + b0v, acc[mi][nj][1] + b1v);
                *(float2*)(y1 + cB) =
                    make_float2(acc[mi][nj][2] + b0v, acc[mi][nj][3] + b1v);
            }
        }
    }
}

// ---------------------------------------------------------------------------
extern "C" void kernel_launch(void* const* d_in, const int* in_sizes, int n_in,
                              void* d_out, int out_size) {
    const float* x  = (const float*)d_in[0];
    const float* gw = (const float*)d_in[1];
    const float* w1 = (const float*)d_in[2];
    const float* b1 = (const float*)d_in[3];
    const float* w2 = (const float*)d_in[4];
    const float* b2 = (const float*)d_in[5];
    float* out = (float*)d_out;

    cudaFuncSetAttribute(mma_gemm<DIN, true>,
                         cudaFuncAttributeMaxDynamicSharedMemorySize, DYN_BYTES);
    cudaFuncSetAttribute(mma_gemm<DHID, false>,
                         cudaFuncAttributeMaxDynamicSharedMemorySize, DYN_BYTES);

    gate_kernel<<<GATE_B + W1CONV_B + XCONV_B, 256>>>(x, gw, (const float4*)w1);
    assign_kernel<<<NEXP, 256>>>();

    mma_gemm<DIN, true><<<dim3(NMT + W2CONV_X, DHID / BN), 128, DYN_BYTES>>>(
        b1, (const float4*)w2);
    mma_gemm<DHID, false><<<dim3(DOUT / BN, NMT), 128, DYN_BYTES>>>(b2, nullptr);
    combine_kernel<<<BATCH, 256>>>(out);
}